// round 15
// baseline (speedup 1.0000x reference)
#include <cuda_runtime.h>
#include <cuda_fp16.h>
#include <cstdint>

// Problem constants
#define BB 8192
#define NN 128
#define HH 1024
#define OO 64      // 2*A
#define AA 32
#define TT 8

#define BH ((size_t)BB * HH)

// ---------------------------------------------------------------------------
// Scratch (device globals — allocation-free per harness rules)
// ---------------------------------------------------------------------------
__device__ uint32_t       g_s1pk[65536 * 32];    // s1 spike BITS: row m=b*8+t, 32 words of k-bits
__device__ unsigned short g_sacc [BH];           // sum_t 2^(t-8) s2(t), fp16 (exact)
__device__ unsigned short g_w2h[1024 * 2048];    // [N=1024][K=2048] fp16 hi|lo
__device__ unsigned short g_w3h[64 * 2048];      // [N=64]  [K=2048] fp16 hi|lo
__device__ float          g_b3s[OO];             // b3 * 255/256

// ---------------------------------------------------------------------------
// PTX helpers (baseline sm_103 ISA: cp.async, ldmatrix, mma.sync fp16)
// ---------------------------------------------------------------------------
__device__ __forceinline__ uint32_t smem_u32(const void* p) {
    uint32_t a;
    asm("{ .reg .u64 t; cvta.to.shared.u64 t, %1; cvt.u32.u64 %0, t; }" : "=r"(a) : "l"(p));
    return a;
}
__device__ __forceinline__ void cp16(uint32_t dst, const void* src) {
    asm volatile("cp.async.cg.shared.global [%0], [%1], 16;" :: "r"(dst), "l"(src));
}
#define CP_COMMIT() asm volatile("cp.async.commit_group;" ::: "memory")
#define CP_WAIT(n)  asm volatile("cp.async.wait_group %0;" :: "n"(n) : "memory")

__device__ __forceinline__ void ldsm4(uint32_t* r, uint32_t a) {
    asm volatile("ldmatrix.sync.aligned.m8n8.x4.shared.b16 {%0,%1,%2,%3}, [%4];"
                 : "=r"(r[0]), "=r"(r[1]), "=r"(r[2]), "=r"(r[3]) : "r"(a));
}
// fp16 HMMA with fp32 accumulation
__device__ __forceinline__ void mma16816(float* c, const uint32_t* a, const uint32_t* b) {
    asm volatile("mma.sync.aligned.m16n8k16.row.col.f32.f16.f16.f32 "
                 "{%0,%1,%2,%3}, {%4,%5,%6,%7}, {%8,%9}, {%0,%1,%2,%3};"
                 : "+f"(c[0]), "+f"(c[1]), "+f"(c[2]), "+f"(c[3])
                 : "r"(a[0]), "r"(a[1]), "r"(a[2]), "r"(a[3]), "r"(b[0]), "r"(b[1]));
}
__device__ __forceinline__ void sts128(uint32_t addr, uint32_t x, uint32_t y,
                                       uint32_t z, uint32_t w) {
    asm volatile("st.shared.v4.b32 [%0], {%1,%2,%3,%4};"
                 :: "r"(addr), "r"(x), "r"(y), "r"(z), "r"(w) : "memory");
}

// ---------------------------------------------------------------------------
// Weight prep via smem tile transpose (coalesced both sides).
// ---------------------------------------------------------------------------
__global__ void prep_w2h(const float* __restrict__ w2) {
    __shared__ float tile[32][33];
    const int bx = blockIdx.x, by = blockIdx.y;
    const int tx = threadIdx.x, ty = threadIdx.y;
#pragma unroll
    for (int i = ty; i < 32; i += 8)
        tile[i][tx] = w2[(size_t)(by * 32 + i) * 1024 + bx * 32 + tx];
    __syncthreads();
#pragma unroll
    for (int i = ty; i < 32; i += 8) {
        int n = bx * 32 + i, k = by * 32 + tx;
        float w = tile[tx][i];
        __half hi = __float2half_rn(w);
        __half lo = __float2half_rn(w - __half2float(hi));
        g_w2h[(size_t)n * 2048 + k]        = __half_as_ushort(hi);
        g_w2h[(size_t)n * 2048 + 1024 + k] = __half_as_ushort(lo);
    }
}
__global__ void prep_w3h(const float* __restrict__ w3, const float* __restrict__ b3) {
    int t = blockIdx.x * blockDim.x + threadIdx.x;            // 64K threads
    if (t >= 64 * 1024) return;
    int n = t & 63, k = t >> 6;
    float w = w3[(size_t)k * 64 + n];
    __half hi = __float2half_rn(w);
    __half lo = __float2half_rn(w - __half2float(hi));
    size_t base = (size_t)n * 2048;
    g_w3h[base + k]        = __half_as_ushort(hi);
    g_w3h[base + 1024 + k] = __half_as_ushort(lo);
    if (t < OO) g_b3s[t] = b3[t] * (255.0f / 256.0f);
}

#define EPAD 132   // padded row length (floats) for the fire2 epilogue tile

// ---------------------------------------------------------------------------
// g1 + fire1 fused (EXACT fp32; single accumulator, ascending k 0..127 —
// bit-identical u to the r12 passing kernel). BM=128, BN=128, BK=16,
// TM=8, TN=8, 256 threads.
// Epilogue: all 8 IF-node-1 steps; spike BITS assembled into pattern bytes
// (nibble + shfl_xor pairing), staged in smem, stored as packed words:
// g_s1pk[m = b*8+t][kw], bit j of byte (kw,pos) <-> col kw*32+pos*8+j.
// ---------------------------------------------------------------------------
__global__ __launch_bounds__(256)
void g1_fire1(const float* __restrict__ A, const float* __restrict__ Bm,
              const float* __restrict__ bias)
{
    constexpr int BK = 16;
    __shared__ float As[BK][128 + 4];   // k-major: As[k][row]
    __shared__ float Bs[BK][128 + 4];   // Bs[k][col]
    __shared__ unsigned char staged[1024 * 16];   // packed bits: [r_loc*8+t][16B]
    const int tid = threadIdx.x;
    const int tx = tid & 15;            // 0..15 (col groups)
    const int ty = tid >> 4;            // 0..15 (row groups of 8)
    const int rowBase = blockIdx.y * 128;
    const int colBase = blockIdx.x * 128;

    float acc[8][8];
#pragma unroll
    for (int i = 0; i < 8; i++)
#pragma unroll
        for (int j = 0; j < 8; j++) acc[i][j] = 0.0f;

    for (int k0 = 0; k0 < NN; k0 += BK) {
#pragma unroll
        for (int i = tid; i < 512; i += 256) {
            int r = i >> 2, k4 = (i & 3) * 4;
            float4 v = *reinterpret_cast<const float4*>(
                A + (size_t)(rowBase + r) * NN + k0 + k4);
            As[k4 + 0][r] = v.x;
            As[k4 + 1][r] = v.y;
            As[k4 + 2][r] = v.z;
            As[k4 + 3][r] = v.w;
        }
#pragma unroll
        for (int i = tid; i < 512; i += 256) {
            int rr = i >> 5, c4 = (i & 31) * 4;
            float4 v = *reinterpret_cast<const float4*>(
                Bm + (size_t)(k0 + rr) * HH + colBase + c4);
            *reinterpret_cast<float4*>(&Bs[rr][c4]) = v;
        }
        __syncthreads();
#pragma unroll
        for (int kk = 0; kk < BK; kk++) {
            float4 ra0 = *reinterpret_cast<const float4*>(&As[kk][ty * 8]);
            float4 ra1 = *reinterpret_cast<const float4*>(&As[kk][ty * 8 + 4]);
            float4 rb0 = *reinterpret_cast<const float4*>(&Bs[kk][tx * 4]);
            float4 rb1 = *reinterpret_cast<const float4*>(&Bs[kk][64 + tx * 4]);
            float ra[8] = { ra0.x, ra0.y, ra0.z, ra0.w, ra1.x, ra1.y, ra1.z, ra1.w };
            float rb[8] = { rb0.x, rb0.y, rb0.z, rb0.w, rb1.x, rb1.y, rb1.z, rb1.w };
#pragma unroll
            for (int i = 0; i < 8; i++)
#pragma unroll
                for (int j = 0; j < 8; j++)
                    acc[i][j] += ra[i] * rb[j];
        }
        __syncthreads();
    }

    // fused fire1: per row, two 4-col quads; pack bits via shfl pairing.
    const int cg0 = colBase + tx * 4;
    const int cg1 = colBase + 64 + tx * 4;
    const float4 bv0 = *reinterpret_cast<const float4*>(bias + cg0);
    const float4 bv1 = *reinterpret_cast<const float4*>(bias + cg1);
    const bool evenlane = ((tx & 1) == 0);
#pragma unroll
    for (int i = 0; i < 8; i++) {
        int stagedr = (ty * 8 + i) * 8;           // r_loc * 8  (+t later)
#pragma unroll
        for (int g = 0; g < 2; g++) {
            float u[4];
            if (g == 0) {
                u[0] = acc[i][0] + bv0.x; u[1] = acc[i][1] + bv0.y;
                u[2] = acc[i][2] + bv0.z; u[3] = acc[i][3] + bv0.w;
            } else {
                u[0] = acc[i][4] + bv1.x; u[1] = acc[i][5] + bv1.y;
                u[2] = acc[i][6] + bv1.z; u[3] = acc[i][7] + bv1.w;
            }
            const int o = g * 8 + (tx >> 1);      // byte index 0..15
            float v1[4] = { 0.0f, 0.0f, 0.0f, 0.0f };
#pragma unroll
            for (int t = 0; t < TT; ++t) {
                float h; int nib = 0;
                h = v1[0] + u[0]; if (h >= 1.0f) { nib |= 1; v1[0] = 0.0f; } else v1[0] = h;
                h = v1[1] + u[1]; if (h >= 1.0f) { nib |= 2; v1[1] = 0.0f; } else v1[1] = h;
                h = v1[2] + u[2]; if (h >= 1.0f) { nib |= 4; v1[2] = 0.0f; } else v1[2] = h;
                h = v1[3] + u[3]; if (h >= 1.0f) { nib |= 8; v1[3] = 0.0f; } else v1[3] = h;
                int other = __shfl_xor_sync(0xffffffffu, nib, 1);
                if (evenlane)
                    staged[(stagedr + t) * 16 + o] = (unsigned char)(nib | (other << 4));
            }
        }
    }
    __syncthreads();

    // coalesced copy of packed bits to global: 1024 rows x 16 B
    const uint4* s4 = reinterpret_cast<const uint4*>(staged);
    uint4* dst = reinterpret_cast<uint4*>(g_s1pk);
#pragma unroll
    for (int j = tid; j < 1024; j += 256) {
        size_t mg = (size_t)(rowBase + (j >> 3)) * 8 + (j & 7);
        dst[mg * 8 + blockIdx.x] = s4[j];
    }
}

// ---------------------------------------------------------------------------
// Big fp16 HMMA GEMM with packed-bit A decode + FUSED fire2 scan.
// A tile is decoded from g_s1pk (1 LDG.32/thread/chunk, prefetched one chunk
// ahead) into the EXACT same swizzled smem bytes the old cp16 path produced.
// B via cp.async as before. Mainloop/fire2 arithmetic identical to r13.
// ---------------------------------------------------------------------------
__global__ __launch_bounds__(256, 2)
void gemm_big(const uint32_t* __restrict__ Apk,
              const unsigned short* __restrict__ Bt,
              const float* __restrict__ b2,
              unsigned short* __restrict__ saccp)
{
    constexpr int BK = 64;
    constexpr int KTOT = 2048;
    constexpr int NIT = KTOT / BK;        // 32
    constexpr int ATB = 128 * 128;
    constexpr int BTB = 128 * 128;
    constexpr int STAGE = ATB + BTB;

    extern __shared__ char dsm[];
    const uint32_t sbase = smem_u32(dsm);

    const int tid = threadIdx.x;
    const int wid = tid >> 5;
    const int lane = tid & 31;
    const int wm = wid & 3;
    const int wn = wid >> 2;
    const int rowBase = blockIdx.y * 128;
    const int colBase = blockIdx.x * 128;

    const int rdec = tid >> 1;            // decode row 0..127
    const int wdec = tid & 1;             // which 32-bit word of the 64-k chunk

    auto ldg_pk = [&](int it) -> uint32_t {
        int kA = (it * 64) & 1023;
        return Apk[(size_t)(rowBase + rdec) * 32 + (kA >> 5) + wdec];
    };
    auto decode_store = [&](int buf, uint32_t pk) {
        const uint32_t sA = sbase + buf * STAGE;
#pragma unroll
        for (int q4 = 0; q4 < 4; ++q4) {
            uint32_t bb = (pk >> (q4 * 8)) & 0xFFu;
            uint32_t x = ((bb & 1u)   ? 0x3C00u : 0u) | ((bb & 2u)   ? 0x3C000000u : 0u);
            uint32_t y = ((bb & 4u)   ? 0x3C00u : 0u) | ((bb & 8u)   ? 0x3C000000u : 0u);
            uint32_t z = ((bb & 16u)  ? 0x3C00u : 0u) | ((bb & 32u)  ? 0x3C000000u : 0u);
            uint32_t w = ((bb & 64u)  ? 0x3C00u : 0u) | ((bb & 128u) ? 0x3C000000u : 0u);
            int q = wdec * 4 + q4;
            sts128(sA + rdec * 128 + ((q ^ (rdec & 7)) << 4), x, y, z, w);
        }
    };
    auto cp_B = [&](int it) {
        const uint32_t sB = sbase + (it % 3) * STAGE + ATB;
        const int kb = it * BK;
#pragma unroll
        for (int i = 0; i < 4; ++i) {
            int idx = i * 256 + tid;
            int r = idx >> 3, q = idx & 7;
            const void* src = Bt + (size_t)(colBase + r) * KTOT + kb + q * 8;
            cp16(sB + r * 128 + ((q ^ (r & 7)) << 4), src);
        }
    };

    float acc[2][8][4];
#pragma unroll
    for (int mt = 0; mt < 2; ++mt)
#pragma unroll
        for (int nt = 0; nt < 8; ++nt)
#pragma unroll
            for (int x = 0; x < 4; ++x) acc[mt][nt][x] = 0.0f;

    // prologue: stages 0 and 1
    uint32_t p0 = ldg_pk(0);
    uint32_t p1 = ldg_pk(1);
    cp_B(0); CP_COMMIT();
    cp_B(1); CP_COMMIT();
    decode_store(0, p0);
    decode_store(1, p1);
    uint32_t pnext = ldg_pk(2);

    const int rA0 = wm * 32 + (lane & 15);
    const int qAsel = lane >> 4;
    const int nB0 = wn * 64 + ((lane >> 4) << 3) + (lane & 7);
    const int qBsel = (lane >> 3) & 1;

    for (int it = 0; it < NIT; ++it) {
        CP_WAIT(1);
        __syncthreads();
        if (it + 2 < NIT) { decode_store((it + 2) % 3, pnext); cp_B(it + 2); }
        CP_COMMIT();
        if (it + 3 < NIT) pnext = ldg_pk(it + 3);

        const uint32_t sA = sbase + (it % 3) * STAGE;
        const uint32_t sB = sA + ATB;

#pragma unroll
        for (int s = 0; s < 4; ++s) {
            uint32_t a[2][4];
#pragma unroll
            for (int mt = 0; mt < 2; ++mt) {
                int r = rA0 + mt * 16;
                int q = 2 * s + qAsel;
                ldsm4(a[mt], sA + r * 128 + ((q ^ (r & 7)) << 4));
            }
            uint32_t b[8][2];
#pragma unroll
            for (int j = 0; j < 8; j += 2) {
                int n = nB0 + j * 8;
                int q = 2 * s + qBsel;
                uint32_t t4[4];
                ldsm4(t4, sB + n * 128 + ((q ^ (n & 7)) << 4));
                b[j][0] = t4[0]; b[j][1] = t4[1];
                b[j + 1][0] = t4[2]; b[j + 1][1] = t4[3];
            }
#pragma unroll
            for (int mt = 0; mt < 2; ++mt)
#pragma unroll
                for (int nt = 0; nt < 8; ++nt)
                    mma16816(acc[mt][nt], a[mt], b[nt]);
        }
    }

    // ---- fused fire2 epilogue via smem (identical to r13) ----
    CP_WAIT(0);
    __syncthreads();
    float* sx = reinterpret_cast<float*>(dsm);

#pragma unroll
    for (int mt = 0; mt < 2; ++mt) {
#pragma unroll
        for (int nt = 0; nt < 8; ++nt) {
            int c = wn * 64 + nt * 8 + (lane & 3) * 2;
#pragma unroll
            for (int hrow = 0; hrow < 2; ++hrow) {
                int m = wm * 32 + mt * 16 + (lane >> 2) + hrow * 8;
                float2 v;
                v.x = acc[mt][nt][hrow * 2 + 0];
                v.y = acc[mt][nt][hrow * 2 + 1];
                *reinterpret_cast<float2*>(&sx[m * EPAD + c]) = v;
            }
        }
    }
    __syncthreads();

    const int bBase = rowBase >> 3;
#pragma unroll
    for (int idx = 0; idx < 2; ++idx) {
        int flat = idx * 256 + tid;
        int bl = flat >> 5;             // 0..15
        int c4 = (flat & 31) * 4;       // 0..124
        const float4 bv = *reinterpret_cast<const float4*>(&b2[colBase + c4]);
        float v2[4] = { 0.0f, 0.0f, 0.0f, 0.0f };
        float sc[4] = { 0.0f, 0.0f, 0.0f, 0.0f };
#pragma unroll
        for (int t = 0; t < TT; ++t) {
            float4 x = *reinterpret_cast<const float4*>(&sx[(bl * 8 + t) * EPAD + c4]);
            float w = (float)(1 << t) * (1.0f / 256.0f);
            float h;
            h = v2[0] + x.x; h = h + bv.x;
            if (h >= 1.0f) { v2[0] = 0.0f; sc[0] += w; } else v2[0] = h;
            h = v2[1] + x.y; h = h + bv.y;
            if (h >= 1.0f) { v2[1] = 0.0f; sc[1] += w; } else v2[1] = h;
            h = v2[2] + x.z; h = h + bv.z;
            if (h >= 1.0f) { v2[2] = 0.0f; sc[2] += w; } else v2[2] = h;
            h = v2[3] + x.w; h = h + bv.w;
            if (h >= 1.0f) { v2[3] = 0.0f; sc[3] += w; } else v2[3] = h;
        }
        ushort4 sv;
        sv.x = __half_as_ushort(__float2half_rn(sc[0]));
        sv.y = __half_as_ushort(__float2half_rn(sc[1]));
        sv.z = __half_as_ushort(__float2half_rn(sc[2]));
        sv.w = __half_as_ushort(__float2half_rn(sc[3]));
        *reinterpret_cast<ushort4*>(
            saccp + (size_t)(bBase + bl) * HH + colBase + c4) = sv;
    }
}

// ---------------------------------------------------------------------------
// g3 + FUSED finalize (r13 verbatim): v3 stays in smem; tanh-Gaussian head
// in-kernel (2 threads per batch row, shfl_xor pair-combine).
// ---------------------------------------------------------------------------
#define VPAD 66

__global__ __launch_bounds__(128)
void gemm_g3_fin(const unsigned short* __restrict__ A,
                 const unsigned short* __restrict__ Bt,
                 const float* __restrict__ bias,
                 const float* __restrict__ eps,
                 float* __restrict__ out)
{
    constexpr int BM = 64, BN = 64, BK = 64;
    constexpr int KTOT = 2048, AK = 1024;
    constexpr int NIT = KTOT / BK;        // 32
    constexpr int STAGES = 3;
    constexpr int ATB = BM * 128;
    constexpr int BTB = BN * 128;
    constexpr int STAGE = ATB + BTB;
    constexpr int WTM = 16;

    extern __shared__ char dsm[];
    const uint32_t sbase = smem_u32(dsm);

    const int tid = threadIdx.x;
    const int wid = tid >> 5;
    const int lane = tid & 31;
    const int wm = wid;
    const int rowBase = blockIdx.y * BM;

    auto load_tile = [&](int buf, int it) {
        const uint32_t sA = sbase + buf * STAGE;
        const uint32_t sB = sA + ATB;
        const int kb = it * BK;
        const int kA = kb & (AK - 1);
#pragma unroll
        for (int i = 0; i < 4; ++i) {
            int idx = i * 128 + tid;
            int r = idx >> 3, q = idx & 7;
            const void* src = A + (size_t)(rowBase + r) * AK + kA + q * 8;
            cp16(sA + r * 128 + ((q ^ (r & 7)) << 4), src);
        }
#pragma unroll
        for (int i = 0; i < 4; ++i) {
            int idx = i * 128 + tid;
            int r = idx >> 3, q = idx & 7;
            const void* src = Bt + (size_t)r * KTOT + kb + q * 8;
            cp16(sB + r * 128 + ((q ^ (r & 7)) << 4), src);
        }
    };

    float acc[8][4];
#pragma unroll
    for (int nt = 0; nt < 8; ++nt)
#pragma unroll
        for (int x = 0; x < 4; ++x) acc[nt][x] = 0.0f;

#pragma unroll
    for (int p = 0; p < STAGES - 1; ++p) { load_tile(p, p); CP_COMMIT(); }

    const int rA0 = wm * WTM + (lane & 15);
    const int qAsel = lane >> 4;
    const int nB0 = (lane >> 4) * 8 + (lane & 7);
    const int qBsel = (lane >> 3) & 1;

    for (int it = 0; it < NIT; ++it) {
        CP_WAIT(1);
        __syncthreads();
        if (it + STAGES - 1 < NIT) load_tile((it + STAGES - 1) % STAGES, it + STAGES - 1);
        CP_COMMIT();

        const uint32_t sA = sbase + (it % STAGES) * STAGE;
        const uint32_t sB = sA + ATB;

#pragma unroll
        for (int s = 0; s < 4; ++s) {
            uint32_t a[4];
            {
                int r = rA0;
                int q = 2 * s + qAsel;
                ldsm4(a, sA + r * 128 + ((q ^ (r & 7)) << 4));
            }
            uint32_t b[8][2];
#pragma unroll
            for (int j = 0; j < 8; j += 2) {
                int n = nB0 + j * 8;
                int q = 2 * s + qBsel;
                uint32_t t4[4];
                ldsm4(t4, sB + n * 128 + ((q ^ (n & 7)) << 4));
                b[j][0] = t4[0]; b[j][1] = t4[1];
                b[j + 1][0] = t4[2]; b[j + 1][1] = t4[3];
            }
#pragma unroll
            for (int nt = 0; nt < 8; ++nt)
                mma16816(acc[nt], a, b[nt]);
        }
    }

    // ---- park v3 tile in smem ----
    CP_WAIT(0);
    __syncthreads();
    float* sv3 = reinterpret_cast<float*>(dsm);   // [64][VPAD]

    int lr0 = wm * WTM + (lane >> 2);
#pragma unroll
    for (int nt = 0; nt < 8; ++nt) {
        int c = nt * 8 + (lane & 3) * 2;
        float bi0 = bias[c], bi1 = bias[c + 1];
#pragma unroll
        for (int hrow = 0; hrow < 2; ++hrow) {
            int lr = lr0 + hrow * 8;
            float2 o;
            o.x = acc[nt][hrow * 2 + 0] + bi0;
            o.y = acc[nt][hrow * 2 + 1] + bi1;
            *reinterpret_cast<float2*>(&sv3[lr * VPAD + c]) = o;
        }
    }
    __syncthreads();

    // ---- fused tanh-Gaussian head: 2 threads per row, 16 actions each ----
    {
        int lr = tid >> 1;            // 0..63
        int half = tid & 1;
        int b = rowBase + lr;
        int a0 = half * 16;
        float lp = 0.0f;
#pragma unroll
        for (int a = a0; a < a0 + 16; ++a) {
            float mu = sv3[lr * VPAD + a];
            float ls = sv3[lr * VPAD + AA + a];
            ls = fminf(fmaxf(ls, -20.0f), 2.0f);
            float sd = expf(ls);
            float e  = eps[(size_t)b * AA + a];
            float z  = mu + sd * e;
            float ac = tanhf(z);
            out[(size_t)b * AA + a] = ac;
            lp += -0.5f * e * e - ls - 0.91893853320467274f
                  - logf(1.0f - ac * ac + 1e-7f);
        }
        lp += __shfl_xor_sync(0xffffffffu, lp, 1);
        if (half == 0) out[(size_t)BB * AA + b] = lp;
    }
}

// ---------------------------------------------------------------------------
extern "C" void kernel_launch(void* const* d_in, const int* in_sizes, int n_in,
                              void* d_out, int out_size)
{
    const float* state = (const float*)d_in[0];
    const float* w1    = (const float*)d_in[1];
    const float* b1    = (const float*)d_in[2];
    const float* w2    = (const float*)d_in[3];
    const float* b2    = (const float*)d_in[4];
    const float* w3    = (const float*)d_in[5];
    const float* b3    = (const float*)d_in[6];
    const float* eps   = (const float*)d_in[7];
    float* out = (float*)d_out;

    uint32_t* s1pk = nullptr; unsigned short* sacc = nullptr;
    unsigned short* w2h = nullptr; unsigned short* w3h = nullptr;
    float* b3s = nullptr;
    cudaGetSymbolAddress((void**)&s1pk, g_s1pk);
    cudaGetSymbolAddress((void**)&sacc, g_sacc);
    cudaGetSymbolAddress((void**)&w2h,  g_w2h);
    cudaGetSymbolAddress((void**)&w3h,  g_w3h);
    cudaGetSymbolAddress((void**)&b3s,  g_b3s);

    const int SMBIG = 3 * (128 * 128 + 128 * 128); // 98304 (>= 128*EPAD*4)
    const int SMG3  = 3 * (64 * 128 + 64 * 128);   // 49152 (>= 64*VPAD*4)
    cudaFuncSetAttribute(gemm_big,    cudaFuncAttributeMaxDynamicSharedMemorySize, SMBIG);
    cudaFuncSetAttribute(gemm_g3_fin, cudaFuncAttributeMaxDynamicSharedMemorySize, SMG3);

    // 1) weight prep (2-term fp16 split; w2 via coalesced tile transpose)
    {
        dim3 blk(32, 8);
        prep_w2h<<<dim3(32, 32), blk>>>(w2);
    }
    prep_w3h<<<(64 * 1024) / 256, 256>>>(w3, b3);

    // 2) g1 (exact fp32, ascending-k — bit-identical u) + fused fire1,
    //    spikes stored as packed bits (8 MB instead of 128 MB)
    {
        dim3 grid(HH / 128, BB / 128);
        g1_fire1<<<grid, 256>>>(state, w1, b1);
    }

    // 3) big fp16 GEMM (packed-bit A decode) + fused fire2 -> sacc
    {
        dim3 grid(HH / 128, (TT * BB) / 128);
        gemm_big<<<grid, 256, SMBIG>>>(s1pk, w2h, b2, sacc);
    }

    // 4) g3 GEMM + fused tanh-Gaussian head
    {
        dim3 grid(1, BB / 64);
        gemm_g3_fin<<<grid, 128, SMG3>>>(sacc, w3h, b3s, eps, out);
    }
}

// round 16
// speedup vs baseline: 1.1980x; 1.1980x over previous
#include <cuda_runtime.h>
#include <cuda_fp16.h>
#include <cstdint>

// Problem constants
#define BB 8192
#define NN 128
#define HH 1024
#define OO 64      // 2*A
#define AA 32
#define TT 8

#define BH ((size_t)BB * HH)

// ---------------------------------------------------------------------------
// Scratch (device globals — allocation-free per harness rules)
// ---------------------------------------------------------------------------
__device__ unsigned short g_s1all[TT * BH];      // s1 spikes, row m = b*8 + t, fp16 bits
__device__ unsigned short g_sacc [BH];           // sum_t 2^(t-8) s2(t), fp16 (exact)
__device__ unsigned short g_w2h[1024 * 2048];    // [N=1024][K=2048] fp16 hi|lo
__device__ unsigned short g_w3h[64 * 2048];      // [N=64]  [K=2048] fp16 hi|lo
__device__ float          g_b3s[OO];             // b3 * 255/256

// ---------------------------------------------------------------------------
// PTX helpers (baseline sm_103 ISA: cp.async, ldmatrix, mma.sync fp16)
// ---------------------------------------------------------------------------
__device__ __forceinline__ uint32_t smem_u32(const void* p) {
    uint32_t a;
    asm("{ .reg .u64 t; cvta.to.shared.u64 t, %1; cvt.u32.u64 %0, t; }" : "=r"(a) : "l"(p));
    return a;
}
__device__ __forceinline__ void cp16(uint32_t dst, const void* src) {
    asm volatile("cp.async.cg.shared.global [%0], [%1], 16;" :: "r"(dst), "l"(src));
}
#define CP_COMMIT() asm volatile("cp.async.commit_group;" ::: "memory")
#define CP_WAIT(n)  asm volatile("cp.async.wait_group %0;" :: "n"(n) : "memory")

__device__ __forceinline__ void ldsm4(uint32_t* r, uint32_t a) {
    asm volatile("ldmatrix.sync.aligned.m8n8.x4.shared.b16 {%0,%1,%2,%3}, [%4];"
                 : "=r"(r[0]), "=r"(r[1]), "=r"(r[2]), "=r"(r[3]) : "r"(a));
}
// fp16 HMMA with fp32 accumulation
__device__ __forceinline__ void mma16816(float* c, const uint32_t* a, const uint32_t* b) {
    asm volatile("mma.sync.aligned.m16n8k16.row.col.f32.f16.f16.f32 "
                 "{%0,%1,%2,%3}, {%4,%5,%6,%7}, {%8,%9}, {%0,%1,%2,%3};"
                 : "+f"(c[0]), "+f"(c[1]), "+f"(c[2]), "+f"(c[3])
                 : "r"(a[0]), "r"(a[1]), "r"(a[2]), "r"(a[3]), "r"(b[0]), "r"(b[1]));
}

// ---------------------------------------------------------------------------
// Weight prep via smem tile transpose (coalesced both sides).
// w2: [k=1024][n=1024] fp32 -> g_w2h [n][2048] fp16 hi|lo
// ---------------------------------------------------------------------------
__global__ void prep_w2h(const float* __restrict__ w2) {
    __shared__ float tile[32][33];
    const int bx = blockIdx.x, by = blockIdx.y;
    const int tx = threadIdx.x, ty = threadIdx.y;
#pragma unroll
    for (int i = ty; i < 32; i += 8)
        tile[i][tx] = w2[(size_t)(by * 32 + i) * 1024 + bx * 32 + tx];
    __syncthreads();
#pragma unroll
    for (int i = ty; i < 32; i += 8) {
        int n = bx * 32 + i, k = by * 32 + tx;
        float w = tile[tx][i];
        __half hi = __float2half_rn(w);
        __half lo = __float2half_rn(w - __half2float(hi));
        g_w2h[(size_t)n * 2048 + k]        = __half_as_ushort(hi);
        g_w2h[(size_t)n * 2048 + 1024 + k] = __half_as_ushort(lo);
    }
}
__global__ void prep_w3h(const float* __restrict__ w3, const float* __restrict__ b3) {
    int t = blockIdx.x * blockDim.x + threadIdx.x;            // 64K threads
    if (t >= 64 * 1024) return;
    int n = t & 63, k = t >> 6;
    float w = w3[(size_t)k * 64 + n];
    __half hi = __float2half_rn(w);
    __half lo = __float2half_rn(w - __half2float(hi));
    size_t base = (size_t)n * 2048;
    g_w3h[base + k]        = __half_as_ushort(hi);
    g_w3h[base + 1024 + k] = __half_as_ushort(lo);
    if (t < OO) g_b3s[t] = b3[t] * (255.0f / 256.0f);
}

#define EPAD 132   // padded row length (floats) for the fire2 epilogue tile

// ---------------------------------------------------------------------------
// g1 + fire1 fused (EXACT fp32; single accumulator, ascending k 0..127 —
// bit-identical u to the r12 passing kernel). BM=128, BN=128, BK=16,
// TM=8, TN=8, 256 threads. ushort4 spike stores, rows m = r*8 + t.
// ---------------------------------------------------------------------------
__global__ __launch_bounds__(256)
void g1_fire1(const float* __restrict__ A, const float* __restrict__ Bm,
              const float* __restrict__ bias)
{
    constexpr int BK = 16;
    __shared__ float As[BK][128 + 4];   // k-major: As[k][row]
    __shared__ float Bs[BK][128 + 4];   // Bs[k][col]
    const int tid = threadIdx.x;
    const int tx = tid & 15;            // 0..15 (col groups)
    const int ty = tid >> 4;            // 0..15 (row groups of 8)
    const int rowBase = blockIdx.y * 128;
    const int colBase = blockIdx.x * 128;

    float acc[8][8];
#pragma unroll
    for (int i = 0; i < 8; i++)
#pragma unroll
        for (int j = 0; j < 8; j++) acc[i][j] = 0.0f;

    for (int k0 = 0; k0 < NN; k0 += BK) {
#pragma unroll
        for (int i = tid; i < 512; i += 256) {
            int r = i >> 2, k4 = (i & 3) * 4;
            float4 v = *reinterpret_cast<const float4*>(
                A + (size_t)(rowBase + r) * NN + k0 + k4);
            As[k4 + 0][r] = v.x;
            As[k4 + 1][r] = v.y;
            As[k4 + 2][r] = v.z;
            As[k4 + 3][r] = v.w;
        }
#pragma unroll
        for (int i = tid; i < 512; i += 256) {
            int rr = i >> 5, c4 = (i & 31) * 4;
            float4 v = *reinterpret_cast<const float4*>(
                Bm + (size_t)(k0 + rr) * HH + colBase + c4);
            *reinterpret_cast<float4*>(&Bs[rr][c4]) = v;
        }
        __syncthreads();
#pragma unroll
        for (int kk = 0; kk < BK; kk++) {
            float4 ra0 = *reinterpret_cast<const float4*>(&As[kk][ty * 8]);
            float4 ra1 = *reinterpret_cast<const float4*>(&As[kk][ty * 8 + 4]);
            float4 rb0 = *reinterpret_cast<const float4*>(&Bs[kk][tx * 4]);
            float4 rb1 = *reinterpret_cast<const float4*>(&Bs[kk][64 + tx * 4]);
            float ra[8] = { ra0.x, ra0.y, ra0.z, ra0.w, ra1.x, ra1.y, ra1.z, ra1.w };
            float rb[8] = { rb0.x, rb0.y, rb0.z, rb0.w, rb1.x, rb1.y, rb1.z, rb1.w };
#pragma unroll
            for (int i = 0; i < 8; i++)
#pragma unroll
                for (int j = 0; j < 8; j++)
                    acc[i][j] += ra[i] * rb[j];
        }
        __syncthreads();
    }

    const int cg0 = colBase + tx * 4;
    const int cg1 = colBase + 64 + tx * 4;
    const float4 bv0 = *reinterpret_cast<const float4*>(bias + cg0);
    const float4 bv1 = *reinterpret_cast<const float4*>(bias + cg1);
#pragma unroll
    for (int i = 0; i < 8; i++) {
        int r = rowBase + ty * 8 + i;
        size_t rowb = (size_t)r * (TT * HH);
#pragma unroll
        for (int g = 0; g < 2; g++) {
            float u[4];
            if (g == 0) {
                u[0] = acc[i][0] + bv0.x; u[1] = acc[i][1] + bv0.y;
                u[2] = acc[i][2] + bv0.z; u[3] = acc[i][3] + bv0.w;
            } else {
                u[0] = acc[i][4] + bv1.x; u[1] = acc[i][5] + bv1.y;
                u[2] = acc[i][6] + bv1.z; u[3] = acc[i][7] + bv1.w;
            }
            int cg = (g == 0) ? cg0 : cg1;
            float v1[4] = { 0.0f, 0.0f, 0.0f, 0.0f };
#pragma unroll
            for (int t = 0; t < TT; ++t) {
                ushort4 sv;
                float h;
                h = v1[0] + u[0]; sv.x = (h >= 1.0f) ? 0x3C00 : 0; v1[0] = (h >= 1.0f) ? 0.0f : h;
                h = v1[1] + u[1]; sv.y = (h >= 1.0f) ? 0x3C00 : 0; v1[1] = (h >= 1.0f) ? 0.0f : h;
                h = v1[2] + u[2]; sv.z = (h >= 1.0f) ? 0x3C00 : 0; v1[2] = (h >= 1.0f) ? 0.0f : h;
                h = v1[3] + u[3]; sv.w = (h >= 1.0f) ? 0x3C00 : 0; v1[3] = (h >= 1.0f) ? 0.0f : h;
                *reinterpret_cast<ushort4*>(g_s1all + rowb + (size_t)t * HH + cg) = sv;
            }
        }
    }
}

// ---------------------------------------------------------------------------
// Big fp16 HMMA GEMM with A-SHARED hi/lo chunks + FUSED fire2 scan.
// 16 chunks of k=64: each loads A once + B_hi(kb) + B_lo(kb+1024); the A
// fragments feed BOTH mma groups (smem reads -17%, A smem writes -50%).
// 2-stage cp.async pipeline (STAGE=48KB, 2 stages = 96KB, 2 CTAs/SM).
// fire2 epilogue identical to r12.
// ---------------------------------------------------------------------------
__global__ __launch_bounds__(256, 2)
void gemm_big(const unsigned short* __restrict__ A,
              const unsigned short* __restrict__ Bt,
              const float* __restrict__ b2,
              unsigned short* __restrict__ saccp)
{
    constexpr int NIT = 16;               // chunks of 64 k (hi+lo per chunk)
    constexpr int ATB = 128 * 128;        // 16384
    constexpr int BTB = 128 * 128;        // 16384 per B tile
    constexpr int STAGE = ATB + 2 * BTB;  // 49152

    extern __shared__ char dsm[];
    const uint32_t sbase = smem_u32(dsm);

    const int tid = threadIdx.x;
    const int wid = tid >> 5;
    const int lane = tid & 31;
    const int wm = wid & 3;
    const int wn = wid >> 2;
    const int rowBase = blockIdx.y * 128;
    const int colBase = blockIdx.x * 128;

    auto load_tile = [&](int buf, int it) {
        const uint32_t sA  = sbase + buf * STAGE;
        const uint32_t sBh = sA + ATB;
        const uint32_t sBl = sBh + BTB;
        const int kb = it * 64;
#pragma unroll
        for (int i = 0; i < 4; ++i) {        // A (once per chunk)
            int idx = i * 256 + tid;
            int r = idx >> 3, q = idx & 7;
            const void* src = A + (size_t)(rowBase + r) * 1024 + kb + q * 8;
            cp16(sA + r * 128 + ((q ^ (r & 7)) << 4), src);
        }
#pragma unroll
        for (int i = 0; i < 4; ++i) {        // B hi term
            int idx = i * 256 + tid;
            int r = idx >> 3, q = idx & 7;
            const void* src = Bt + (size_t)(colBase + r) * 2048 + kb + q * 8;
            cp16(sBh + r * 128 + ((q ^ (r & 7)) << 4), src);
        }
#pragma unroll
        for (int i = 0; i < 4; ++i) {        // B lo term
            int idx = i * 256 + tid;
            int r = idx >> 3, q = idx & 7;
            const void* src = Bt + (size_t)(colBase + r) * 2048 + 1024 + kb + q * 8;
            cp16(sBl + r * 128 + ((q ^ (r & 7)) << 4), src);
        }
    };

    float acc[2][8][4];
#pragma unroll
    for (int mt = 0; mt < 2; ++mt)
#pragma unroll
        for (int nt = 0; nt < 8; ++nt)
#pragma unroll
            for (int x = 0; x < 4; ++x) acc[mt][nt][x] = 0.0f;

    load_tile(0, 0); CP_COMMIT();
    load_tile(1, 1); CP_COMMIT();

    const int rA0 = wm * 32 + (lane & 15);
    const int qAsel = lane >> 4;
    const int nB0 = wn * 64 + ((lane >> 4) << 3) + (lane & 7);
    const int qBsel = (lane >> 3) & 1;

    for (int it = 0; it < NIT; ++it) {
        CP_WAIT(1);
        __syncthreads();

        const uint32_t sA  = sbase + (it & 1) * STAGE;
        const uint32_t sBh = sA + ATB;
        const uint32_t sBl = sBh + BTB;

#pragma unroll
        for (int s = 0; s < 4; ++s) {
            uint32_t a[2][4];
#pragma unroll
            for (int mt = 0; mt < 2; ++mt) {
                int r = rA0 + mt * 16;
                int q = 2 * s + qAsel;
                ldsm4(a[mt], sA + r * 128 + ((q ^ (r & 7)) << 4));
            }
            // hi term
            {
                uint32_t b[8][2];
#pragma unroll
                for (int j = 0; j < 8; j += 2) {
                    int n = nB0 + j * 8;
                    int q = 2 * s + qBsel;
                    uint32_t t4[4];
                    ldsm4(t4, sBh + n * 128 + ((q ^ (n & 7)) << 4));
                    b[j][0] = t4[0]; b[j][1] = t4[1];
                    b[j + 1][0] = t4[2]; b[j + 1][1] = t4[3];
                }
#pragma unroll
                for (int mt = 0; mt < 2; ++mt)
#pragma unroll
                    for (int nt = 0; nt < 8; ++nt)
                        mma16816(acc[mt][nt], a[mt], b[nt]);
            }
            // lo term (reuses A fragments)
            {
                uint32_t b[8][2];
#pragma unroll
                for (int j = 0; j < 8; j += 2) {
                    int n = nB0 + j * 8;
                    int q = 2 * s + qBsel;
                    uint32_t t4[4];
                    ldsm4(t4, sBl + n * 128 + ((q ^ (n & 7)) << 4));
                    b[j][0] = t4[0]; b[j][1] = t4[1];
                    b[j + 1][0] = t4[2]; b[j + 1][1] = t4[3];
                }
#pragma unroll
                for (int mt = 0; mt < 2; ++mt)
#pragma unroll
                    for (int nt = 0; nt < 8; ++nt)
                        mma16816(acc[mt][nt], a[mt], b[nt]);
            }
        }

        __syncthreads();
        if (it + 2 < NIT) load_tile(it & 1, it + 2);
        CP_COMMIT();
    }

    // ---- fused fire2 epilogue via smem (identical to r12) ----
    CP_WAIT(0);
    __syncthreads();
    float* sx = reinterpret_cast<float*>(dsm);

#pragma unroll
    for (int mt = 0; mt < 2; ++mt) {
#pragma unroll
        for (int nt = 0; nt < 8; ++nt) {
            int c = wn * 64 + nt * 8 + (lane & 3) * 2;
#pragma unroll
            for (int hrow = 0; hrow < 2; ++hrow) {
                int m = wm * 32 + mt * 16 + (lane >> 2) + hrow * 8;
                float2 v;
                v.x = acc[mt][nt][hrow * 2 + 0];
                v.y = acc[mt][nt][hrow * 2 + 1];
                *reinterpret_cast<float2*>(&sx[m * EPAD + c]) = v;
            }
        }
    }
    __syncthreads();

    const int bBase = rowBase >> 3;
#pragma unroll
    for (int idx = 0; idx < 2; ++idx) {
        int flat = idx * 256 + tid;
        int bl = flat >> 5;             // 0..15
        int c4 = (flat & 31) * 4;       // 0..124
        const float4 bv = *reinterpret_cast<const float4*>(&b2[colBase + c4]);
        float v2[4] = { 0.0f, 0.0f, 0.0f, 0.0f };
        float sc[4] = { 0.0f, 0.0f, 0.0f, 0.0f };
#pragma unroll
        for (int t = 0; t < TT; ++t) {
            float4 x = *reinterpret_cast<const float4*>(&sx[(bl * 8 + t) * EPAD + c4]);
            float w = (float)(1 << t) * (1.0f / 256.0f);
            float h;
            h = v2[0] + x.x; h = h + bv.x;
            if (h >= 1.0f) { v2[0] = 0.0f; sc[0] += w; } else v2[0] = h;
            h = v2[1] + x.y; h = h + bv.y;
            if (h >= 1.0f) { v2[1] = 0.0f; sc[1] += w; } else v2[1] = h;
            h = v2[2] + x.z; h = h + bv.z;
            if (h >= 1.0f) { v2[2] = 0.0f; sc[2] += w; } else v2[2] = h;
            h = v2[3] + x.w; h = h + bv.w;
            if (h >= 1.0f) { v2[3] = 0.0f; sc[3] += w; } else v2[3] = h;
        }
        ushort4 sv;
        sv.x = __half_as_ushort(__float2half_rn(sc[0]));
        sv.y = __half_as_ushort(__float2half_rn(sc[1]));
        sv.z = __half_as_ushort(__float2half_rn(sc[2]));
        sv.w = __half_as_ushort(__float2half_rn(sc[3]));
        *reinterpret_cast<ushort4*>(
            saccp + (size_t)(bBase + bl) * HH + colBase + c4) = sv;
    }
}

// ---------------------------------------------------------------------------
// g3 + FUSED finalize: v3 stays in smem; tanh-Gaussian head in-kernel.
// BM=64, 4 warps / 128 threads, grid 128 CTAs.
// ---------------------------------------------------------------------------
#define VPAD 66

__global__ __launch_bounds__(128)
void gemm_g3_fin(const unsigned short* __restrict__ A,
                 const unsigned short* __restrict__ Bt,
                 const float* __restrict__ bias,
                 const float* __restrict__ eps,
                 float* __restrict__ out)
{
    constexpr int BM = 64, BN = 64, BK = 64;
    constexpr int KTOT = 2048, AK = 1024;
    constexpr int NIT = KTOT / BK;        // 32
    constexpr int STAGES = 3;
    constexpr int ATB = BM * 128;
    constexpr int BTB = BN * 128;
    constexpr int STAGE = ATB + BTB;
    constexpr int WTM = 16;

    extern __shared__ char dsm[];
    const uint32_t sbase = smem_u32(dsm);

    const int tid = threadIdx.x;
    const int wid = tid >> 5;
    const int lane = tid & 31;
    const int wm = wid;
    const int rowBase = blockIdx.y * BM;

    auto load_tile = [&](int buf, int it) {
        const uint32_t sA = sbase + buf * STAGE;
        const uint32_t sB = sA + ATB;
        const int kb = it * BK;
        const int kA = kb & (AK - 1);
#pragma unroll
        for (int i = 0; i < 4; ++i) {
            int idx = i * 128 + tid;
            int r = idx >> 3, q = idx & 7;
            const void* src = A + (size_t)(rowBase + r) * AK + kA + q * 8;
            cp16(sA + r * 128 + ((q ^ (r & 7)) << 4), src);
        }
#pragma unroll
        for (int i = 0; i < 4; ++i) {
            int idx = i * 128 + tid;
            int r = idx >> 3, q = idx & 7;
            const void* src = Bt + (size_t)r * KTOT + kb + q * 8;
            cp16(sB + r * 128 + ((q ^ (r & 7)) << 4), src);
        }
    };

    float acc[8][4];
#pragma unroll
    for (int nt = 0; nt < 8; ++nt)
#pragma unroll
        for (int x = 0; x < 4; ++x) acc[nt][x] = 0.0f;

#pragma unroll
    for (int p = 0; p < STAGES - 1; ++p) { load_tile(p, p); CP_COMMIT(); }

    const int rA0 = wm * WTM + (lane & 15);
    const int qAsel = lane >> 4;
    const int nB0 = (lane >> 4) * 8 + (lane & 7);
    const int qBsel = (lane >> 3) & 1;

    for (int it = 0; it < NIT; ++it) {
        CP_WAIT(1);
        __syncthreads();
        if (it + STAGES - 1 < NIT) load_tile((it + STAGES - 1) % STAGES, it + STAGES - 1);
        CP_COMMIT();

        const uint32_t sA = sbase + (it % STAGES) * STAGE;
        const uint32_t sB = sA + ATB;

#pragma unroll
        for (int s = 0; s < 4; ++s) {
            uint32_t a[4];
            {
                int r = rA0;
                int q = 2 * s + qAsel;
                ldsm4(a, sA + r * 128 + ((q ^ (r & 7)) << 4));
            }
            uint32_t b[8][2];
#pragma unroll
            for (int j = 0; j < 8; j += 2) {
                int n = nB0 + j * 8;
                int q = 2 * s + qBsel;
                uint32_t t4[4];
                ldsm4(t4, sB + n * 128 + ((q ^ (n & 7)) << 4));
                b[j][0] = t4[0]; b[j][1] = t4[1];
                b[j + 1][0] = t4[2]; b[j + 1][1] = t4[3];
            }
#pragma unroll
            for (int nt = 0; nt < 8; ++nt)
                mma16816(acc[nt], a, b[nt]);
        }
    }

    // ---- park v3 tile in smem ----
    CP_WAIT(0);
    __syncthreads();
    float* sv3 = reinterpret_cast<float*>(dsm);   // [64][VPAD]

    int lr0 = wm * WTM + (lane >> 2);
#pragma unroll
    for (int nt = 0; nt < 8; ++nt) {
        int c = nt * 8 + (lane & 3) * 2;
        float bi0 = bias[c], bi1 = bias[c + 1];
#pragma unroll
        for (int hrow = 0; hrow < 2; ++hrow) {
            int lr = lr0 + hrow * 8;
            float2 o;
            o.x = acc[nt][hrow * 2 + 0] + bi0;
            o.y = acc[nt][hrow * 2 + 1] + bi1;
            *reinterpret_cast<float2*>(&sv3[lr * VPAD + c]) = o;
        }
    }
    __syncthreads();

    // ---- fused tanh-Gaussian head: 2 threads per row, 16 actions each ----
    {
        int lr = tid >> 1;            // 0..63
        int half = tid & 1;
        int b = rowBase + lr;
        int a0 = half * 16;
        float lp = 0.0f;
#pragma unroll
        for (int a = a0; a < a0 + 16; ++a) {
            float mu = sv3[lr * VPAD + a];
            float ls = sv3[lr * VPAD + AA + a];
            ls = fminf(fmaxf(ls, -20.0f), 2.0f);
            float sd = expf(ls);
            float e  = eps[(size_t)b * AA + a];
            float z  = mu + sd * e;
            float ac = tanhf(z);
            out[(size_t)b * AA + a] = ac;
            lp += -0.5f * e * e - ls - 0.91893853320467274f
                  - logf(1.0f - ac * ac + 1e-7f);
        }
        lp += __shfl_xor_sync(0xffffffffu, lp, 1);
        if (half == 0) out[(size_t)BB * AA + b] = lp;
    }
}

// ---------------------------------------------------------------------------
extern "C" void kernel_launch(void* const* d_in, const int* in_sizes, int n_in,
                              void* d_out, int out_size)
{
    const float* state = (const float*)d_in[0];
    const float* w1    = (const float*)d_in[1];
    const float* b1    = (const float*)d_in[2];
    const float* w2    = (const float*)d_in[3];
    const float* b2    = (const float*)d_in[4];
    const float* w3    = (const float*)d_in[5];
    const float* b3    = (const float*)d_in[6];
    const float* eps   = (const float*)d_in[7];
    float* out = (float*)d_out;

    unsigned short* s1all = nullptr; unsigned short* sacc = nullptr;
    unsigned short* w2h = nullptr; unsigned short* w3h = nullptr;
    float* b3s = nullptr;
    cudaGetSymbolAddress((void**)&s1all, g_s1all);
    cudaGetSymbolAddress((void**)&sacc,  g_sacc);
    cudaGetSymbolAddress((void**)&w2h,   g_w2h);
    cudaGetSymbolAddress((void**)&w3h,   g_w3h);
    cudaGetSymbolAddress((void**)&b3s,   g_b3s);

    const int SMBIG = 2 * (128 * 128 + 2 * 128 * 128); // 98304 (>= 128*EPAD*4)
    const int SMG3  = 3 * (64 * 128 + 64 * 128);       // 49152 (>= 64*VPAD*4)
    cudaFuncSetAttribute(gemm_big,    cudaFuncAttributeMaxDynamicSharedMemorySize, SMBIG);
    cudaFuncSetAttribute(gemm_g3_fin, cudaFuncAttributeMaxDynamicSharedMemorySize, SMG3);

    // 1) weight prep (2-term fp16 split; w2 via coalesced tile transpose)
    {
        dim3 blk(32, 8);
        prep_w2h<<<dim3(32, 32), blk>>>(w2);
    }
    prep_w3h<<<(64 * 1024) / 256, 256>>>(w3, b3);

    // 2) g1 (exact fp32, ascending-k — bit-identical u) + fused fire1
    {
        dim3 grid(HH / 128, BB / 128);
        g1_fire1<<<grid, 256>>>(state, w1, b1);
    }

    // 3) big fp16 GEMM (A shared across hi/lo) + fused fire2 -> sacc
    {
        dim3 grid(HH / 128, (TT * BB) / 128);
        gemm_big<<<grid, 256, SMBIG>>>(s1all, w2h, b2, sacc);
    }

    // 4) g3 GEMM + fused tanh-Gaussian head
    {
        dim3 grid(1, BB / 64);
        gemm_g3_fin<<<grid, 128, SMG3>>>(sacc, w3h, b3s, eps, out);
    }
}